// round 3
// baseline (speedup 1.0000x reference)
#include <cuda_runtime.h>
#include <cuda_bf16.h>
#include <stdint.h>
#include <math.h>

// Problem dims
#define T_      16384      // B*S tokens
#define D_      1024
#define E_      64
#define NE_     128        // gate + noise logits concatenated
#define NNOISE  1048576    // T_*E_

// Output layout (all float32, tuple order, flattened)
#define OUT_RW    0
#define OUT_IDX   32768
#define OUT_LOSS  65536
#define OUT_PROBS 65537
#define OUT_NSM   1114113

// Scratch (device globals)
__device__ float g_logits[T_ * NE_];   // [t][0..63]=clean, [t][64..127]=noise-lin
__device__ float g_sumprob[E_];
__device__ int   g_tok[E_];
__device__ float g_nssum;
__device__ __nv_bfloat16 g_Wh[NE_ * D_];   // W split: high bf16
__device__ __nv_bfloat16 g_Wm[NE_ * D_];   // W split: mid  bf16

// ---------------------------------------------------------------------------
// Threefry-2x32 (JAX-exact)
// ---------------------------------------------------------------------------
__host__ __device__ __forceinline__ uint32_t rotl32(uint32_t v, int d) {
    return (v << d) | (v >> (32 - d));
}

__host__ __device__ __forceinline__ void tf2x32(uint32_t k0, uint32_t k1,
                                                uint32_t x0, uint32_t x1,
                                                uint32_t& o0, uint32_t& o1) {
    uint32_t ks0 = k0, ks1 = k1, ks2 = 0x1BD11BDAu ^ k0 ^ k1;
    x0 += ks0; x1 += ks1;
    x0 += x1; x1 = rotl32(x1, 13); x1 ^= x0;
    x0 += x1; x1 = rotl32(x1, 15); x1 ^= x0;
    x0 += x1; x1 = rotl32(x1, 26); x1 ^= x0;
    x0 += x1; x1 = rotl32(x1,  6); x1 ^= x0;
    x0 += ks1; x1 += ks2 + 1u;
    x0 += x1; x1 = rotl32(x1, 17); x1 ^= x0;
    x0 += x1; x1 = rotl32(x1, 29); x1 ^= x0;
    x0 += x1; x1 = rotl32(x1, 16); x1 ^= x0;
    x0 += x1; x1 = rotl32(x1, 24); x1 ^= x0;
    x0 += ks2; x1 += ks0 + 2u;
    x0 += x1; x1 = rotl32(x1, 13); x1 ^= x0;
    x0 += x1; x1 = rotl32(x1, 15); x1 ^= x0;
    x0 += x1; x1 = rotl32(x1, 26); x1 ^= x0;
    x0 += x1; x1 = rotl32(x1,  6); x1 ^= x0;
    x0 += ks0; x1 += ks1 + 3u;
    x0 += x1; x1 = rotl32(x1, 17); x1 ^= x0;
    x0 += x1; x1 = rotl32(x1, 29); x1 ^= x0;
    x0 += x1; x1 = rotl32(x1, 16); x1 ^= x0;
    x0 += x1; x1 = rotl32(x1, 24); x1 ^= x0;
    x0 += ks1; x1 += ks2 + 4u;
    x0 += x1; x1 = rotl32(x1, 13); x1 ^= x0;
    x0 += x1; x1 = rotl32(x1, 15); x1 ^= x0;
    x0 += x1; x1 = rotl32(x1, 26); x1 ^= x0;
    x0 += x1; x1 = rotl32(x1,  6); x1 ^= x0;
    x0 += ks2; x1 += ks0 + 5u;
    o0 = x0; o1 = x1;
}

__device__ __forceinline__ float erfinv_xla(float x) {
    float w = -log1pf(-x * x);
    float p;
    if (w < 5.0f) {
        w -= 2.5f;
        p = 2.81022636e-08f;
        p = fmaf(p, w, 3.43273939e-07f);
        p = fmaf(p, w, -3.5233877e-06f);
        p = fmaf(p, w, -4.39150654e-06f);
        p = fmaf(p, w, 0.00021858087f);
        p = fmaf(p, w, -0.00125372503f);
        p = fmaf(p, w, -0.00417768164f);
        p = fmaf(p, w, 0.246640727f);
        p = fmaf(p, w, 1.50140941f);
    } else {
        w = sqrtf(w) - 3.0f;
        p = -0.000200214257f;
        p = fmaf(p, w, 0.000100950558f);
        p = fmaf(p, w, 0.00134934322f);
        p = fmaf(p, w, -0.00367342844f);
        p = fmaf(p, w, 0.00573950773f);
        p = fmaf(p, w, -0.0076224613f);
        p = fmaf(p, w, 0.00943887047f);
        p = fmaf(p, w, 1.00167406f);
        p = fmaf(p, w, 2.83297682f);
    }
    return p * x;
}

__device__ __forceinline__ float jax_normal(uint32_t k0, uint32_t k1, uint32_t i) {
    uint32_t b1, b2;
    tf2x32(k0, k1, 0u, i, b1, b2);
    uint32_t bits = b1 ^ b2;
    float f = __uint_as_float((bits >> 9) | 0x3F800000u) - 1.0f;
    const float lo = -0.99999994039535522461f;
    float u = fmaf(f, 2.0f, lo);
    u = fmaxf(u, lo);
    return 1.41421353816986083984f * erfinv_xla(u);
}

__device__ __forceinline__ float softplus_f(float x) {
    return fmaxf(x, 0.0f) + log1pf(expf(-fabsf(x)));
}

// ---------------------------------------------------------------------------
// mma.sync helpers (base PTX ISA, safe at target sm_103)
// ---------------------------------------------------------------------------
__device__ __forceinline__ uint32_t smem_u32(const void* p) {
    uint32_t a;
    asm("{ .reg .u64 t; cvta.to.shared.u64 t, %1; cvt.u32.u64 %0, t; }" : "=r"(a) : "l"(p));
    return a;
}

__device__ __forceinline__ void ldsm_x4(uint32_t* r, uint32_t addr) {
    asm volatile("ldmatrix.sync.aligned.m8n8.x4.shared.b16 {%0,%1,%2,%3}, [%4];"
                 : "=r"(r[0]), "=r"(r[1]), "=r"(r[2]), "=r"(r[3]) : "r"(addr));
}

__device__ __forceinline__ void ldsm_x2(uint32_t* r, uint32_t addr) {
    asm volatile("ldmatrix.sync.aligned.m8n8.x2.shared.b16 {%0,%1}, [%2];"
                 : "=r"(r[0]), "=r"(r[1]) : "r"(addr));
}

__device__ __forceinline__ void mma16816(float* d, const uint32_t* a, const uint32_t* b) {
    asm volatile(
        "mma.sync.aligned.m16n8k16.row.col.f32.bf16.bf16.f32 "
        "{%0,%1,%2,%3}, {%4,%5,%6,%7}, {%8,%9}, {%0,%1,%2,%3};"
        : "+f"(d[0]), "+f"(d[1]), "+f"(d[2]), "+f"(d[3])
        : "r"(a[0]), "r"(a[1]), "r"(a[2]), "r"(a[3]), "r"(b[0]), "r"(b[1]));
}

__device__ __forceinline__ void cpasync16(uint32_t dst, const void* src) {
    asm volatile("cp.async.cg.shared.global [%0], [%1], 16;" :: "r"(dst), "l"(src) : "memory");
}

// ---------------------------------------------------------------------------
// W split prep: g_Wh/g_Wm = bf16 split of [W_gate; W_noise]
// ---------------------------------------------------------------------------
__global__ void prep_w_kernel(const float* __restrict__ Wg, const float* __restrict__ Wn) {
    int idx = blockIdx.x * 256 + threadIdx.x;     // grid 512 -> 131072 elems
    int r = idx >> 10, k = idx & 1023;
    float v = (r < E_) ? Wg[r * D_ + k] : Wn[(r - E_) * D_ + k];
    __nv_bfloat16 h = __float2bfloat16_rn(v);
    float rem = v - __bfloat162float(h);
    g_Wh[idx] = h;
    g_Wm[idx] = __float2bfloat16_rn(rem);
}

// ---------------------------------------------------------------------------
// HMMA split-bf16 GEMM: g_logits[128 tokens][128 cols] per CTA
// 3 terms: Xh*Wh + Xh*Wm + Xm*Wh. K chunks of 64, double buffered.
// ---------------------------------------------------------------------------
#define BM      128
#define BK      64
#define STR     72                       // padded bf16 row stride
#define ASPLIT  (BM * STR * 2)           // 18432 B per split tile
#define BUFB    (4 * ASPLIT)             // Xh,Xm,Wh,Wm = 73728 B
#define SMEM_TOT (2 * BUFB)              // 147456 B

__global__ __launch_bounds__(256, 1) void gemm_mma_kernel(const float* __restrict__ X) {
    extern __shared__ char smem[];
    const uint32_t sb = smem_u32(smem);
    const int tid = threadIdx.x;
    const int lane = tid & 31, wid = tid >> 5;
    const int m0 = blockIdx.x * BM;

    float4 xr[8];

    // --- load helpers ---
    auto load_x = [&](int kt) {
#pragma unroll
        for (int it = 0; it < 8; it++) {
            int idx = tid + it * 256;
            int r = idx >> 4, c4 = (idx & 15) << 2;
            xr[it] = *(const float4*)(X + (size_t)(m0 + r) * D_ + kt * BK + c4);
        }
    };
    auto store_x = [&](int buf) {
        uint32_t base = sb + buf * BUFB;
#pragma unroll
        for (int it = 0; it < 8; it++) {
            int idx = tid + it * 256;
            int r = idx >> 4, c4 = (idx & 15) << 2;
            uint32_t off = (uint32_t)(r * STR + c4) * 2;
            float v[4] = {xr[it].x, xr[it].y, xr[it].z, xr[it].w};
            uint32_t hp[2], mp[2];
#pragma unroll
            for (int q = 0; q < 2; q++) {
                __nv_bfloat162 h = __floats2bfloat162_rn(v[2 * q], v[2 * q + 1]);
                float r0 = v[2 * q]     - __bfloat162float(h.x);
                float r1 = v[2 * q + 1] - __bfloat162float(h.y);
                __nv_bfloat162 m = __floats2bfloat162_rn(r0, r1);
                hp[q] = *(uint32_t*)&h;
                mp[q] = *(uint32_t*)&m;
            }
            asm volatile("st.shared.v2.b32 [%0], {%1,%2};" :: "r"(base + off), "r"(hp[0]), "r"(hp[1]) : "memory");
            asm volatile("st.shared.v2.b32 [%0], {%1,%2};" :: "r"(base + ASPLIT + off), "r"(mp[0]), "r"(mp[1]) : "memory");
        }
    };
    auto load_w = [&](int kt, int buf) {
        uint32_t bbase = sb + buf * BUFB + 2 * ASPLIT;
#pragma unroll
        for (int it = 0; it < 4; it++) {
            int idx = tid + it * 256;
            int r = idx >> 3, c8 = (idx & 7) << 3;
            uint32_t off = (uint32_t)(r * STR + c8) * 2;
            cpasync16(bbase + off,          g_Wh + (size_t)r * D_ + kt * BK + c8);
            cpasync16(bbase + ASPLIT + off, g_Wm + (size_t)r * D_ + kt * BK + c8);
        }
        asm volatile("cp.async.commit_group;" ::: "memory");
    };

    const int wm = wid & 1, wn = wid >> 1;    // warp tile: 64 rows x 32 cols
    float acc[4][4][4];
#pragma unroll
    for (int a = 0; a < 4; a++)
#pragma unroll
        for (int b = 0; b < 4; b++)
#pragma unroll
            for (int c = 0; c < 4; c++) acc[a][b][c] = 0.0f;

    // prologue: fill buffer 0
    load_x(0);
    load_w(0, 0);
    store_x(0);
    asm volatile("cp.async.wait_group 0;" ::: "memory");
    __syncthreads();

    for (int kt = 0; kt < 16; kt++) {
        const int buf = kt & 1;
        if (kt + 1 < 16) { load_x(kt + 1); load_w(kt + 1, buf ^ 1); }

        const uint32_t Ab = sb + buf * BUFB;
        const uint32_t Bb = Ab + 2 * ASPLIT;
#pragma unroll
        for (int s = 0; s < 4; s++) {
            const int k0 = s * 16;
            uint32_t ah[4][4], am[4][4], bh[4][2], bm[4][2];
            const int aRow = wm * 64 + (lane & 15);
            const int aCol = k0 + ((lane >> 4) << 3);
#pragma unroll
            for (int mt = 0; mt < 4; mt++) {
                uint32_t ad = Ab + (uint32_t)((aRow + mt * 16) * STR + aCol) * 2;
                ldsm_x4(ah[mt], ad);
                ldsm_x4(am[mt], ad + ASPLIT);
            }
            const int bRow = wn * 32 + (lane & 7);
            const int bCol = k0 + (((lane >> 3) & 1) << 3);
#pragma unroll
            for (int nt = 0; nt < 4; nt++) {
                uint32_t bd = Bb + (uint32_t)((bRow + nt * 8) * STR + bCol) * 2;
                ldsm_x2(bh[nt], bd);
                ldsm_x2(bm[nt], bd + ASPLIT);
            }
#pragma unroll
            for (int mt = 0; mt < 4; mt++)
#pragma unroll
                for (int nt = 0; nt < 4; nt++) {
                    mma16816(acc[mt][nt], ah[mt], bh[nt]);
                    mma16816(acc[mt][nt], ah[mt], bm[nt]);
                    mma16816(acc[mt][nt], am[mt], bh[nt]);
                }
        }
        if (kt + 1 < 16) {
            store_x(buf ^ 1);
            asm volatile("cp.async.wait_group 0;" ::: "memory");
        }
        __syncthreads();
    }

    // epilogue: write fp32 logits
    const int row = m0 + wm * 64 + (lane >> 2);
    const int col = wn * 32 + ((lane & 3) << 1);
#pragma unroll
    for (int mt = 0; mt < 4; mt++)
#pragma unroll
        for (int nt = 0; nt < 4; nt++) {
            *(float2*)(g_logits + (size_t)(row + mt * 16) * NE_ + col + nt * 8) =
                make_float2(acc[mt][nt][0], acc[mt][nt][1]);
            *(float2*)(g_logits + (size_t)(row + mt * 16 + 8) * NE_ + col + nt * 8) =
                make_float2(acc[mt][nt][2], acc[mt][nt][3]);
        }
}

// ---------------------------------------------------------------------------
// Router epilogue: warp per token, z-based top-2 + exact fixup for near-ties
// ---------------------------------------------------------------------------
#define MARGIN 5e-4f

__device__ __forceinline__ float dot1024(const float* __restrict__ a,
                                         const float* __restrict__ b) {
    float s0 = 0.f, s1 = 0.f, s2 = 0.f, s3 = 0.f;
#pragma unroll 4
    for (int k = 0; k < D_; k += 4) {
        s0 = fmaf(a[k],     b[k],     s0);
        s1 = fmaf(a[k + 1], b[k + 1], s1);
        s2 = fmaf(a[k + 2], b[k + 2], s2);
        s3 = fmaf(a[k + 3], b[k + 3], s3);
    }
    return (s0 + s1) + (s2 + s3);
}

__global__ __launch_bounds__(256) void router_kernel(float* __restrict__ out,
                                                     const float* __restrict__ X,
                                                     const float* __restrict__ Wg,
                                                     const float* __restrict__ Wn,
                                                     uint32_t k0, uint32_t k1) {
    __shared__ float s_prob[E_];
    __shared__ int   s_tok[E_];
    __shared__ float s_ns;
    const int tid = threadIdx.x;
    if (tid < E_) { s_prob[tid] = 0.0f; s_tok[tid] = 0; }
    if (tid == 0) s_ns = 0.0f;
    __syncthreads();

    const int warp = tid >> 5, lane = tid & 31;
    const int t = blockIdx.x * 8 + warp;
    const float* row = g_logits + (size_t)t * NE_;

    float c0 = row[lane],      c1 = row[32 + lane];
    float n0 = row[64 + lane], n1 = row[96 + lane];
    float sp0 = softplus_f(n0), sp1 = softplus_f(n1);

    const float nv0 = jax_normal(k0, k1, (uint32_t)(t * 64 + lane));
    const float nv1 = jax_normal(k0, k1, (uint32_t)(t * 64 + 32 + lane));
    float z0 = c0 + nv0 * sp0;
    float z1 = c1 + nv1 * sp1;

    const unsigned FULL = 0xFFFFFFFFu;
    const int e0 = lane, e1 = lane + 32;

    // --- top-3 by z (tie -> lower index) ---
    float bv; int bi;
    float m1v, m2v, m3v; int m1i, m2i;

    bv = z0; bi = e0; if (z1 > bv) { bv = z1; bi = e1; }
#pragma unroll
    for (int off = 16; off; off >>= 1) {
        float ov = __shfl_xor_sync(FULL, bv, off);
        int   oi = __shfl_xor_sync(FULL, bi, off);
        if (ov > bv || (ov == bv && oi < bi)) { bv = ov; bi = oi; }
    }
    m1v = bv; m1i = bi;

    float cz0 = (e0 == m1i) ? -INFINITY : z0;
    float cz1 = (e1 == m1i) ? -INFINITY : z1;
    bv = cz0; bi = e0; if (cz1 > bv) { bv = cz1; bi = e1; }
#pragma unroll
    for (int off = 16; off; off >>= 1) {
        float ov = __shfl_xor_sync(FULL, bv, off);
        int   oi = __shfl_xor_sync(FULL, bi, off);
        if (ov > bv || (ov == bv && oi < bi)) { bv = ov; bi = oi; }
    }
    m2v = bv; m2i = bi;

    float dz0 = (e0 == m1i || e0 == m2i) ? -INFINITY : z0;
    float dz1 = (e1 == m1i || e1 == m2i) ? -INFINITY : z1;
    bv = fmaxf(dz0, dz1);
#pragma unroll
    for (int off = 16; off; off >>= 1) bv = fmaxf(bv, __shfl_xor_sync(FULL, bv, off));
    m3v = bv;

    // --- exact fixup for near-ties ---
    if ((m1v - m2v < MARGIN) || (m2v - m3v < MARGIN)) {
        const float thr = m3v - MARGIN;
        const float* xrow = X + (size_t)t * D_;
        if (z0 >= thr) {
            float ce = dot1024(xrow, Wg + (size_t)e0 * D_);
            float ne = dot1024(xrow, Wn + (size_t)e0 * D_);
            z0 = ce + nv0 * softplus_f(ne);
        }
        if (z1 >= thr) {
            float ce = dot1024(xrow, Wg + (size_t)e1 * D_);
            float ne = dot1024(xrow, Wn + (size_t)e1 * D_);
            z1 = ce + nv1 * softplus_f(ne);
        }
        bv = z0; bi = e0; if (z1 > bv) { bv = z1; bi = e1; }
#pragma unroll
        for (int off = 16; off; off >>= 1) {
            float ov = __shfl_xor_sync(FULL, bv, off);
            int   oi = __shfl_xor_sync(FULL, bi, off);
            if (ov > bv || (ov == bv && oi < bi)) { bv = ov; bi = oi; }
        }
        m1v = bv; m1i = bi;
        cz0 = (e0 == m1i) ? -INFINITY : z0;
        cz1 = (e1 == m1i) ? -INFINITY : z1;
        bv = cz0; bi = e0; if (cz1 > bv) { bv = cz1; bi = e1; }
#pragma unroll
        for (int off = 16; off; off >>= 1) {
            float ov = __shfl_xor_sync(FULL, bv, off);
            int   oi = __shfl_xor_sync(FULL, bi, off);
            if (ov > bv || (ov == bv && oi < bi)) { bv = ov; bi = oi; }
        }
        m2v = bv; m2i = bi;
    }

    // routing weights: w1 = p1/(p1+p2) = 1/(1+e^{z2-z1})
    const float e21 = expf(m2v - m1v);
    const float w1 = 1.0f / (1.0f + e21);
    const float w2 = e21 / (1.0f + e21);

    // clean softmax -> router_probs
    float mc = fmaxf(c0, c1);
#pragma unroll
    for (int off = 16; off; off >>= 1) mc = fmaxf(mc, __shfl_xor_sync(FULL, mc, off));
    float q0 = expf(c0 - mc), q1 = expf(c1 - mc);
    float sc = q0 + q1;
#pragma unroll
    for (int off = 16; off; off >>= 1) sc += __shfl_xor_sync(FULL, sc, off);
    q0 /= sc; q1 /= sc;

    out[OUT_PROBS + (size_t)t * E_ + lane]      = q0;
    out[OUT_PROBS + (size_t)t * E_ + 32 + lane] = q1;

    float ns = sp0 + sp1;
#pragma unroll
    for (int off = 16; off; off >>= 1) ns += __shfl_xor_sync(FULL, ns, off);

    if (lane == 0) {
        out[OUT_RW  + t * 2 + 0] = w1;
        out[OUT_RW  + t * 2 + 1] = w2;
        out[OUT_IDX + t * 2 + 0] = (float)m1i;
        out[OUT_IDX + t * 2 + 1] = (float)m2i;
        atomicAdd(&s_tok[m1i], 1);
        atomicAdd(&s_tok[m2i], 1);
        atomicAdd(&s_ns, ns);
    }
    atomicAdd(&s_prob[lane],      q0);
    atomicAdd(&s_prob[lane + 32], q1);

    __syncthreads();
    if (tid < E_) {
        atomicAdd(&g_sumprob[tid], s_prob[tid]);
        atomicAdd(&g_tok[tid], s_tok[tid]);
    }
    if (tid == 0) atomicAdd(&g_nssum, s_ns);
}

__global__ void init_kernel() {
    int i = threadIdx.x;
    if (i < E_) { g_sumprob[i] = 0.0f; g_tok[i] = 0; }
    if (i == 0) g_nssum = 0.0f;
}

__global__ void finalize_kernel(float* __restrict__ out) {
    __shared__ float sh[E_];
    int e = threadIdx.x;
    sh[e] = ((float)g_tok[e] / (float)T_) * (g_sumprob[e] / (float)T_);
    __syncthreads();
    if (e == 0) {
        float acc = 0.0f;
        for (int i = 0; i < E_; i++) acc += sh[i];
        out[OUT_LOSS] = 0.01f * 64.0f * acc;
        out[OUT_NSM]  = g_nssum / (float)NNOISE;
    }
}

// ---------------------------------------------------------------------------
extern "C" void kernel_launch(void* const* d_in, const int* in_sizes, int n_in,
                              void* d_out, int out_size) {
    const float* x  = (const float*)d_in[0];
    const float* Wg = (const float*)d_in[1];
    const float* Wn = (const float*)d_in[2];
    float* out = (float*)d_out;

    uint32_t nk0, nk1;
    tf2x32(0u, 0u, 0u, 12345u, nk0, nk1);

    static bool attr_set = false;
    if (!attr_set) {
        cudaFuncSetAttribute(gemm_mma_kernel, cudaFuncAttributeMaxDynamicSharedMemorySize, SMEM_TOT);
        attr_set = true;
    }

    init_kernel<<<1, 64>>>();
    prep_w_kernel<<<512, 256>>>(Wg, Wn);
    gemm_mma_kernel<<<T_ / BM, 256, SMEM_TOT>>>(x);
    router_kernel<<<T_ / 8, 256>>>(out, x, Wg, Wn, nk0, nk1);
    finalize_kernel<<<1, 64>>>(out);
}

// round 4
// speedup vs baseline: 2.4182x; 2.4182x over previous
#include <cuda_runtime.h>
#include <cuda_bf16.h>
#include <stdint.h>
#include <math.h>

// Problem dims
#define T_      16384      // B*S tokens
#define D_      1024
#define E_      64
#define NE_     128        // gate + noise logits concatenated
#define NNOISE  1048576    // T_*E_

// Output layout (all float32, tuple order, flattened)
#define OUT_RW    0
#define OUT_IDX   32768
#define OUT_LOSS  65536
#define OUT_PROBS 65537
#define OUT_NSM   1114113

// Scratch (device globals)
__device__ float g_logits[T_ * NE_];   // [t][0..63]=clean, [t][64..127]=noise-lin
__device__ float g_sumprob[E_];
__device__ int   g_tok[E_];
__device__ float g_nssum;
__device__ __nv_bfloat16 g_Wh[NE_ * D_];   // W split: high bf16
__device__ __nv_bfloat16 g_Wm[NE_ * D_];   // W split: mid  bf16

// ---------------------------------------------------------------------------
// Threefry-2x32 (JAX-exact)
// ---------------------------------------------------------------------------
__host__ __device__ __forceinline__ uint32_t rotl32(uint32_t v, int d) {
    return (v << d) | (v >> (32 - d));
}

__host__ __device__ __forceinline__ void tf2x32(uint32_t k0, uint32_t k1,
                                                uint32_t x0, uint32_t x1,
                                                uint32_t& o0, uint32_t& o1) {
    uint32_t ks0 = k0, ks1 = k1, ks2 = 0x1BD11BDAu ^ k0 ^ k1;
    x0 += ks0; x1 += ks1;
    x0 += x1; x1 = rotl32(x1, 13); x1 ^= x0;
    x0 += x1; x1 = rotl32(x1, 15); x1 ^= x0;
    x0 += x1; x1 = rotl32(x1, 26); x1 ^= x0;
    x0 += x1; x1 = rotl32(x1,  6); x1 ^= x0;
    x0 += ks1; x1 += ks2 + 1u;
    x0 += x1; x1 = rotl32(x1, 17); x1 ^= x0;
    x0 += x1; x1 = rotl32(x1, 29); x1 ^= x0;
    x0 += x1; x1 = rotl32(x1, 16); x1 ^= x0;
    x0 += x1; x1 = rotl32(x1, 24); x1 ^= x0;
    x0 += ks2; x1 += ks0 + 2u;
    x0 += x1; x1 = rotl32(x1, 13); x1 ^= x0;
    x0 += x1; x1 = rotl32(x1, 15); x1 ^= x0;
    x0 += x1; x1 = rotl32(x1, 26); x1 ^= x0;
    x0 += x1; x1 = rotl32(x1,  6); x1 ^= x0;
    x0 += ks0; x1 += ks1 + 3u;
    x0 += x1; x1 = rotl32(x1, 17); x1 ^= x0;
    x0 += x1; x1 = rotl32(x1, 29); x1 ^= x0;
    x0 += x1; x1 = rotl32(x1, 16); x1 ^= x0;
    x0 += x1; x1 = rotl32(x1, 24); x1 ^= x0;
    x0 += ks1; x1 += ks2 + 4u;
    x0 += x1; x1 = rotl32(x1, 13); x1 ^= x0;
    x0 += x1; x1 = rotl32(x1, 15); x1 ^= x0;
    x0 += x1; x1 = rotl32(x1, 26); x1 ^= x0;
    x0 += x1; x1 = rotl32(x1,  6); x1 ^= x0;
    x0 += ks2; x1 += ks0 + 5u;
    o0 = x0; o1 = x1;
}

__device__ __forceinline__ float erfinv_xla(float x) {
    float w = -log1pf(-x * x);
    float p;
    if (w < 5.0f) {
        w -= 2.5f;
        p = 2.81022636e-08f;
        p = fmaf(p, w, 3.43273939e-07f);
        p = fmaf(p, w, -3.5233877e-06f);
        p = fmaf(p, w, -4.39150654e-06f);
        p = fmaf(p, w, 0.00021858087f);
        p = fmaf(p, w, -0.00125372503f);
        p = fmaf(p, w, -0.00417768164f);
        p = fmaf(p, w, 0.246640727f);
        p = fmaf(p, w, 1.50140941f);
    } else {
        w = sqrtf(w) - 3.0f;
        p = -0.000200214257f;
        p = fmaf(p, w, 0.000100950558f);
        p = fmaf(p, w, 0.00134934322f);
        p = fmaf(p, w, -0.00367342844f);
        p = fmaf(p, w, 0.00573950773f);
        p = fmaf(p, w, -0.0076224613f);
        p = fmaf(p, w, 0.00943887047f);
        p = fmaf(p, w, 1.00167406f);
        p = fmaf(p, w, 2.83297682f);
    }
    return p * x;
}

__device__ __forceinline__ float jax_normal(uint32_t k0, uint32_t k1, uint32_t i) {
    uint32_t b1, b2;
    tf2x32(k0, k1, 0u, i, b1, b2);
    uint32_t bits = b1 ^ b2;
    float f = __uint_as_float((bits >> 9) | 0x3F800000u) - 1.0f;
    const float lo = -0.99999994039535522461f;
    float u = fmaf(f, 2.0f, lo);
    u = fmaxf(u, lo);
    return 1.41421353816986083984f * erfinv_xla(u);
}

__device__ __forceinline__ float softplus_f(float x) {
    return fmaxf(x, 0.0f) + log1pf(expf(-fabsf(x)));
}

// ---------------------------------------------------------------------------
// mma.sync helpers (base PTX ISA, safe at target sm_103)
// ---------------------------------------------------------------------------
__device__ __forceinline__ uint32_t smem_u32(const void* p) {
    uint32_t a;
    asm("{ .reg .u64 t; cvta.to.shared.u64 t, %1; cvt.u32.u64 %0, t; }" : "=r"(a) : "l"(p));
    return a;
}

__device__ __forceinline__ void ldsm_x4(uint32_t* r, uint32_t addr) {
    asm volatile("ldmatrix.sync.aligned.m8n8.x4.shared.b16 {%0,%1,%2,%3}, [%4];"
                 : "=r"(r[0]), "=r"(r[1]), "=r"(r[2]), "=r"(r[3]) : "r"(addr));
}

__device__ __forceinline__ void ldsm_x2(uint32_t* r, uint32_t addr) {
    asm volatile("ldmatrix.sync.aligned.m8n8.x2.shared.b16 {%0,%1}, [%2];"
                 : "=r"(r[0]), "=r"(r[1]) : "r"(addr));
}

__device__ __forceinline__ void mma16816(float* d, const uint32_t* a, const uint32_t* b) {
    asm volatile(
        "mma.sync.aligned.m16n8k16.row.col.f32.bf16.bf16.f32 "
        "{%0,%1,%2,%3}, {%4,%5,%6,%7}, {%8,%9}, {%0,%1,%2,%3};"
        : "+f"(d[0]), "+f"(d[1]), "+f"(d[2]), "+f"(d[3])
        : "r"(a[0]), "r"(a[1]), "r"(a[2]), "r"(a[3]), "r"(b[0]), "r"(b[1]));
}

__device__ __forceinline__ void cpasync16(uint32_t dst, const void* src) {
    asm volatile("cp.async.cg.shared.global [%0], [%1], 16;" :: "r"(dst), "l"(src) : "memory");
}

// ---------------------------------------------------------------------------
// W split prep
// ---------------------------------------------------------------------------
__global__ void prep_w_kernel(const float* __restrict__ Wg, const float* __restrict__ Wn) {
    int idx = blockIdx.x * 256 + threadIdx.x;
    int r = idx >> 10, k = idx & 1023;
    float v = (r < E_) ? Wg[r * D_ + k] : Wn[(r - E_) * D_ + k];
    __nv_bfloat16 h = __float2bfloat16_rn(v);
    float rem = v - __bfloat162float(h);
    g_Wh[idx] = h;
    g_Wm[idx] = __float2bfloat16_rn(rem);
}

// ---------------------------------------------------------------------------
// HMMA split-bf16 GEMM (unchanged from R3 — measured ~10us, rel_err 5.8e-6)
// ---------------------------------------------------------------------------
#define BM      128
#define BK      64
#define STR     72
#define ASPLIT  (BM * STR * 2)
#define BUFB    (4 * ASPLIT)
#define SMEM_TOT (2 * BUFB)

__global__ __launch_bounds__(256, 1) void gemm_mma_kernel(const float* __restrict__ X) {
    extern __shared__ char smem[];
    const uint32_t sb = smem_u32(smem);
    const int tid = threadIdx.x;
    const int lane = tid & 31, wid = tid >> 5;
    const int m0 = blockIdx.x * BM;

    float4 xr[8];

    auto load_x = [&](int kt) {
#pragma unroll
        for (int it = 0; it < 8; it++) {
            int idx = tid + it * 256;
            int r = idx >> 4, c4 = (idx & 15) << 2;
            xr[it] = *(const float4*)(X + (size_t)(m0 + r) * D_ + kt * BK + c4);
        }
    };
    auto store_x = [&](int buf) {
        uint32_t base = sb + buf * BUFB;
#pragma unroll
        for (int it = 0; it < 8; it++) {
            int idx = tid + it * 256;
            int r = idx >> 4, c4 = (idx & 15) << 2;
            uint32_t off = (uint32_t)(r * STR + c4) * 2;
            float v[4] = {xr[it].x, xr[it].y, xr[it].z, xr[it].w};
            uint32_t hp[2], mp[2];
#pragma unroll
            for (int q = 0; q < 2; q++) {
                __nv_bfloat162 h = __floats2bfloat162_rn(v[2 * q], v[2 * q + 1]);
                float r0 = v[2 * q]     - __bfloat162float(h.x);
                float r1 = v[2 * q + 1] - __bfloat162float(h.y);
                __nv_bfloat162 m = __floats2bfloat162_rn(r0, r1);
                hp[q] = *(uint32_t*)&h;
                mp[q] = *(uint32_t*)&m;
            }
            asm volatile("st.shared.v2.b32 [%0], {%1,%2};" :: "r"(base + off), "r"(hp[0]), "r"(hp[1]) : "memory");
            asm volatile("st.shared.v2.b32 [%0], {%1,%2};" :: "r"(base + ASPLIT + off), "r"(mp[0]), "r"(mp[1]) : "memory");
        }
    };
    auto load_w = [&](int kt, int buf) {
        uint32_t bbase = sb + buf * BUFB + 2 * ASPLIT;
#pragma unroll
        for (int it = 0; it < 4; it++) {
            int idx = tid + it * 256;
            int r = idx >> 3, c8 = (idx & 7) << 3;
            uint32_t off = (uint32_t)(r * STR + c8) * 2;
            cpasync16(bbase + off,          g_Wh + (size_t)r * D_ + kt * BK + c8);
            cpasync16(bbase + ASPLIT + off, g_Wm + (size_t)r * D_ + kt * BK + c8);
        }
        asm volatile("cp.async.commit_group;" ::: "memory");
    };

    const int wm = wid & 1, wn = wid >> 1;
    float acc[4][4][4];
#pragma unroll
    for (int a = 0; a < 4; a++)
#pragma unroll
        for (int b = 0; b < 4; b++)
#pragma unroll
            for (int c = 0; c < 4; c++) acc[a][b][c] = 0.0f;

    load_x(0);
    load_w(0, 0);
    store_x(0);
    asm volatile("cp.async.wait_group 0;" ::: "memory");
    __syncthreads();

    for (int kt = 0; kt < 16; kt++) {
        const int buf = kt & 1;
        if (kt + 1 < 16) { load_x(kt + 1); load_w(kt + 1, buf ^ 1); }

        const uint32_t Ab = sb + buf * BUFB;
        const uint32_t Bb = Ab + 2 * ASPLIT;
#pragma unroll
        for (int s = 0; s < 4; s++) {
            const int k0 = s * 16;
            uint32_t ah[4][4], am[4][4], bh[4][2], bm[4][2];
            const int aRow = wm * 64 + (lane & 15);
            const int aCol = k0 + ((lane >> 4) << 3);
#pragma unroll
            for (int mt = 0; mt < 4; mt++) {
                uint32_t ad = Ab + (uint32_t)((aRow + mt * 16) * STR + aCol) * 2;
                ldsm_x4(ah[mt], ad);
                ldsm_x4(am[mt], ad + ASPLIT);
            }
            const int bRow = wn * 32 + (lane & 7);
            const int bCol = k0 + (((lane >> 3) & 1) << 3);
#pragma unroll
            for (int nt = 0; nt < 4; nt++) {
                uint32_t bd = Bb + (uint32_t)((bRow + nt * 8) * STR + bCol) * 2;
                ldsm_x2(bh[nt], bd);
                ldsm_x2(bm[nt], bd + ASPLIT);
            }
#pragma unroll
            for (int mt = 0; mt < 4; mt++)
#pragma unroll
                for (int nt = 0; nt < 4; nt++) {
                    mma16816(acc[mt][nt], ah[mt], bh[nt]);
                    mma16816(acc[mt][nt], ah[mt], bm[nt]);
                    mma16816(acc[mt][nt], am[mt], bh[nt]);
                }
        }
        if (kt + 1 < 16) {
            store_x(buf ^ 1);
            asm volatile("cp.async.wait_group 0;" ::: "memory");
        }
        __syncthreads();
    }

    const int row = m0 + wm * 64 + (lane >> 2);
    const int col = wn * 32 + ((lane & 3) << 1);
#pragma unroll
    for (int mt = 0; mt < 4; mt++)
#pragma unroll
        for (int nt = 0; nt < 4; nt++) {
            *(float2*)(g_logits + (size_t)(row + mt * 16) * NE_ + col + nt * 8) =
                make_float2(acc[mt][nt][0], acc[mt][nt][1]);
            *(float2*)(g_logits + (size_t)(row + mt * 16 + 8) * NE_ + col + nt * 8) =
                make_float2(acc[mt][nt][2], acc[mt][nt][3]);
        }
}

// ---------------------------------------------------------------------------
// Router: warp per token; warp-cooperative exact fixup for near-ties
// ---------------------------------------------------------------------------
#define MARGIN 2e-4f

// Warp-cooperative 1024-dot: x row preloaded in xv[8] (lane l owns elements
// [l*4 + j*128, +4) for j=0..7). Returns full dot on all lanes.
__device__ __forceinline__ float coop_dot(const float4* xv, const float* __restrict__ W,
                                          int lane) {
    float s = 0.f;
#pragma unroll
    for (int j = 0; j < 8; j++) {
        float4 w = *(const float4*)(W + lane * 4 + j * 128);
        s = fmaf(xv[j].x, w.x, s);
        s = fmaf(xv[j].y, w.y, s);
        s = fmaf(xv[j].z, w.z, s);
        s = fmaf(xv[j].w, w.w, s);
    }
#pragma unroll
    for (int off = 16; off; off >>= 1) s += __shfl_xor_sync(0xFFFFFFFFu, s, off);
    return s;
}

__global__ __launch_bounds__(256) void router_kernel(float* __restrict__ out,
                                                     const float* __restrict__ X,
                                                     const float* __restrict__ Wg,
                                                     const float* __restrict__ Wn,
                                                     uint32_t k0, uint32_t k1) {
    __shared__ float s_prob[E_];
    __shared__ int   s_tok[E_];
    __shared__ float s_ns;
    const int tid = threadIdx.x;
    if (tid < E_) { s_prob[tid] = 0.0f; s_tok[tid] = 0; }
    if (tid == 0) s_ns = 0.0f;
    __syncthreads();

    const int warp = tid >> 5, lane = tid & 31;
    const int t = blockIdx.x * 8 + warp;
    const float* row = g_logits + (size_t)t * NE_;

    float c0 = row[lane],      c1 = row[32 + lane];
    float n0 = row[64 + lane], n1 = row[96 + lane];
    float sp0 = softplus_f(n0), sp1 = softplus_f(n1);

    const float nv0 = jax_normal(k0, k1, (uint32_t)(t * 64 + lane));
    const float nv1 = jax_normal(k0, k1, (uint32_t)(t * 64 + 32 + lane));
    float z0 = c0 + nv0 * sp0;
    float z1 = c1 + nv1 * sp1;

    const unsigned FULL = 0xFFFFFFFFu;
    const int e0 = lane, e1 = lane + 32;

    // --- top-3 by z (tie -> lower index) ---
    float bv; int bi;
    float m1v, m2v, m3v; int m1i, m2i;

    bv = z0; bi = e0; if (z1 > bv) { bv = z1; bi = e1; }
#pragma unroll
    for (int off = 16; off; off >>= 1) {
        float ov = __shfl_xor_sync(FULL, bv, off);
        int   oi = __shfl_xor_sync(FULL, bi, off);
        if (ov > bv || (ov == bv && oi < bi)) { bv = ov; bi = oi; }
    }
    m1v = bv; m1i = bi;

    float cz0 = (e0 == m1i) ? -INFINITY : z0;
    float cz1 = (e1 == m1i) ? -INFINITY : z1;
    bv = cz0; bi = e0; if (cz1 > bv) { bv = cz1; bi = e1; }
#pragma unroll
    for (int off = 16; off; off >>= 1) {
        float ov = __shfl_xor_sync(FULL, bv, off);
        int   oi = __shfl_xor_sync(FULL, bi, off);
        if (ov > bv || (ov == bv && oi < bi)) { bv = ov; bi = oi; }
    }
    m2v = bv; m2i = bi;

    float dz0 = (e0 == m1i || e0 == m2i) ? -INFINITY : z0;
    float dz1 = (e1 == m1i || e1 == m2i) ? -INFINITY : z1;
    bv = fmaxf(dz0, dz1);
#pragma unroll
    for (int off = 16; off; off >>= 1) bv = fmaxf(bv, __shfl_xor_sync(FULL, bv, off));
    m3v = bv;

    // --- warp-cooperative exact fixup for near-ties ---
    if ((m1v - m2v < MARGIN) || (m2v - m3v < MARGIN)) {
        const float thr = m2v - MARGIN;
        // preload x row cooperatively: lane owns [lane*4 + j*128, +4)
        const float* xrow = X + (size_t)t * D_;
        float4 xv[8];
#pragma unroll
        for (int j = 0; j < 8; j++) xv[j] = *(const float4*)(xrow + lane * 4 + j * 128);

        unsigned mask0 = __ballot_sync(FULL, z0 >= thr);
        unsigned mask1 = __ballot_sync(FULL, z1 >= thr);

        float b1v = -INFINITY, b2v = -INFINITY;
        int   b1i = 0, b2i = 0;
        // iterate candidates in increasing expert index (ties keep first)
        while (mask0 | mask1) {
            int l0 = mask0 ? __ffs(mask0) - 1 : 64;
            int l1 = mask1 ? __ffs(mask1) - 1 : 64;
            int e; float nv;
            if (l0 <= l1) { e = l0;      nv = __shfl_sync(FULL, nv0, l0); mask0 &= mask0 - 1; }
            else          { e = l1 + 32; nv = __shfl_sync(FULL, nv1, l1); mask1 &= mask1 - 1; }
            float ce = coop_dot(xv, Wg + (size_t)e * D_, lane);
            float ne = coop_dot(xv, Wn + (size_t)e * D_, lane);
            float ze = ce + nv * softplus_f(ne);
            if (ze > b1v) { b2v = b1v; b2i = b1i; b1v = ze; b1i = e; }
            else if (ze > b2v) { b2v = ze; b2i = e; }
        }
        m1v = b1v; m1i = b1i;
        m2v = b2v; m2i = b2i;
    }

    // routing weights: w1 = 1/(1+e^{z2-z1})
    const float e21 = expf(m2v - m1v);
    const float w1 = 1.0f / (1.0f + e21);
    const float w2 = e21 / (1.0f + e21);

    // clean softmax -> router_probs
    float mc = fmaxf(c0, c1);
#pragma unroll
    for (int off = 16; off; off >>= 1) mc = fmaxf(mc, __shfl_xor_sync(FULL, mc, off));
    float q0 = expf(c0 - mc), q1 = expf(c1 - mc);
    float sc = q0 + q1;
#pragma unroll
    for (int off = 16; off; off >>= 1) sc += __shfl_xor_sync(FULL, sc, off);
    q0 /= sc; q1 /= sc;

    out[OUT_PROBS + (size_t)t * E_ + lane]      = q0;
    out[OUT_PROBS + (size_t)t * E_ + 32 + lane] = q1;

    float ns = sp0 + sp1;
#pragma unroll
    for (int off = 16; off; off >>= 1) ns += __shfl_xor_sync(FULL, ns, off);

    if (lane == 0) {
        out[OUT_RW  + t * 2 + 0] = w1;
        out[OUT_RW  + t * 2 + 1] = w2;
        out[OUT_IDX + t * 2 + 0] = (float)m1i;
        out[OUT_IDX + t * 2 + 1] = (float)m2i;
        atomicAdd(&s_tok[m1i], 1);
        atomicAdd(&s_tok[m2i], 1);
        atomicAdd(&s_ns, ns);
    }
    atomicAdd(&s_prob[lane],      q0);
    atomicAdd(&s_prob[lane + 32], q1);

    __syncthreads();
    if (tid < E_) {
        atomicAdd(&g_sumprob[tid], s_prob[tid]);
        atomicAdd(&g_tok[tid], s_tok[tid]);
    }
    if (tid == 0) atomicAdd(&g_nssum, s_ns);
}

__global__ void init_kernel() {
    int i = threadIdx.x;
    if (i < E_) { g_sumprob[i] = 0.0f; g_tok[i] = 0; }
    if (i == 0) g_nssum = 0.0f;
}

__global__ void finalize_kernel(float* __restrict__ out) {
    __shared__ float sh[E_];
    int e = threadIdx.x;
    sh[e] = ((float)g_tok[e] / (float)T_) * (g_sumprob[e] / (float)T_);
    __syncthreads();
    if (e == 0) {
        float acc = 0.0f;
        for (int i = 0; i < E_; i++) acc += sh[i];
        out[OUT_LOSS] = 0.01f * 64.0f * acc;
        out[OUT_NSM]  = g_nssum / (float)NNOISE;
    }
}

// ---------------------------------------------------------------------------
extern "C" void kernel_launch(void* const* d_in, const int* in_sizes, int n_in,
                              void* d_out, int out_size) {
    const float* x  = (const float*)d_in[0];
    const float* Wg = (const float*)d_in[1];
    const float* Wn = (const float*)d_in[2];
    float* out = (float*)d_out;

    uint32_t nk0, nk1;
    tf2x32(0u, 0u, 0u, 12345u, nk0, nk1);

    static bool attr_set = false;
    if (!attr_set) {
        cudaFuncSetAttribute(gemm_mma_kernel, cudaFuncAttributeMaxDynamicSharedMemorySize, SMEM_TOT);
        attr_set = true;
    }

    init_kernel<<<1, 64>>>();
    prep_w_kernel<<<512, 256>>>(Wg, Wn);
    gemm_mma_kernel<<<T_ / BM, 256, SMEM_TOT>>>(x);
    router_kernel<<<T_ / 8, 256>>>(out, x, Wg, Wn, nk0, nk1);
    finalize_kernel<<<1, 64>>>(out);
}